// round 12
// baseline (speedup 1.0000x reference)
#include <cuda_runtime.h>
#include <cuda_bf16.h>
#include <cuda_pipeline.h>
#include <cstdint>

// DeltaNet fused recurrent decode step (all buffers float32; bf16 rounding
// emulated to match the reference exactly).
//   s1  = bf16(exp(gate) * state) ; acc = k^T s1 ; delta = beta*(v - acc)
//   s2  = bf16(s1 + k (outer) delta) ; out = bf16(q^T s2)
//
// One CTA per (b,h). cp.async 3-stage pipeline streams the 64KB f32 state
// tile through a 12KB smem ring; decayed bf16 state cached in 32KB smem for
// pass 2. Insertion input order, element counts, f32 output.

static __device__ __forceinline__ float bf16r(float x) {
    return __bfloat162float(__float2bfloat16(x));
}

// ---------------- Fast path: DK = DV = 128 ----------------
static constexpr int D   = 128;
static constexpr int RPS = 8;            // rows per pipeline stage
static constexpr int NCH = D / RPS;      // 16 chunks
static constexpr int NST = 3;            // ring buffers (2 loads in flight)

__global__ void __launch_bounds__(128)
deltanet_pipe_128(const float* __restrict__ q,
                  const float* __restrict__ k,
                  const float* __restrict__ v,
                  const float* __restrict__ beta,
                  const float* __restrict__ gate,
                  const float* __restrict__ state,
                  float* __restrict__ out)
{
    __shared__ __align__(16) float         raw[NST][RPS * D];   // 12 KB ring
    __shared__ __align__(16) __nv_bfloat16 s1sm[D * D];         // 32 KB decayed state
    __shared__ float ksm[D];
    __shared__ float qsm[D];
    __shared__ __align__(16) float red[4][D];                   // 2 KB partials
    // total 47.0 KB static -> 4 CTAs/SM

    const int bh  = blockIdx.x;
    const int t   = threadIdx.x;
    const int g   = t >> 5;       // row-group within stage (4 groups x 2 rows)
    const int c   = t & 31;
    const int col = 4 * c;        // 4 dv columns per thread

    const float* st = state + (size_t)bh * (D * D);

    // issue one 4KB stage (8 rows x 512B); 2 x 16B per thread, L1-bypassing .cg
    auto issue = [&](int s) {
        const float* src = st + (size_t)s * (RPS * D);
        float* dst = raw[s % NST];
        __pipeline_memcpy_async(dst + t * 4,         src + t * 4,         16);
        __pipeline_memcpy_async(dst + (t + 128) * 4, src + (t + 128) * 4, 16);
        __pipeline_commit();
    };

    issue(0);
    issue(1);

    ksm[t] = __ldg(k + (size_t)bh * D + t);
    qsm[t] = __ldg(q + (size_t)bh * D + t);
    const float decay = expf(__ldg(gate + bh));
    const float betaf = __ldg(beta + bh);

    // ---- Pass 1: stream state, s1 = bf16(decay*S) -> smem, acc = k^T s1 ----
    float acc0 = 0.f, acc1 = 0.f, acc2 = 0.f, acc3 = 0.f;

    for (int s = 0; s < NCH; ++s) {
        __pipeline_wait_prior(1);   // stage s landed (commits are uniform, see tail)
        __syncthreads();            // cross-thread visibility (also covers ksm/qsm)

        if (s + 2 < NCH) issue(s + 2);
        else             __pipeline_commit();   // empty group keeps counts uniform

        const float* buf = raw[s % NST];
#pragma unroll
        for (int e = 0; e < 2; ++e) {
            const int rloc = 2 * g + e;
            const int r    = s * RPS + rloc;
            const float4 f = *reinterpret_cast<const float4*>(buf + rloc * D + col);

            // bf16 round-to-nearest-even after decay (reference stores s1 as bf16)
            const __nv_bfloat162 p01 =
                __float22bfloat162_rn(make_float2(f.x * decay, f.y * decay));
            const __nv_bfloat162 p23 =
                __float22bfloat162_rn(make_float2(f.z * decay, f.w * decay));

            uint2 pk;
            pk.x = *reinterpret_cast<const uint32_t*>(&p01);
            pk.y = *reinterpret_cast<const uint32_t*>(&p23);
            *reinterpret_cast<uint2*>(s1sm + r * D + col) = pk;

            const float kf = ksm[r];
            acc0 += kf * __low2float(p01);
            acc1 += kf * __high2float(p01);
            acc2 += kf * __low2float(p23);
            acc3 += kf * __high2float(p23);
        }
    }

    *reinterpret_cast<float4*>(&red[g][col]) = make_float4(acc0, acc1, acc2, acc3);
    __syncthreads();

    float delta[4];
#pragma unroll
    for (int j = 0; j < 4; ++j) {
        const float a = red[0][col + j] + red[1][col + j] +
                        red[2][col + j] + red[3][col + j];
        const float vf = __ldg(v + (size_t)bh * D + col + j);
        delta[j] = betaf * (vf - a);
    }
    __syncthreads();   // red consumed before pass-2 overwrites it

    // ---- Pass 2: out = q^T bf16(s1 + k*delta), s1 from smem (same rows) ----
    float o0 = 0.f, o1 = 0.f, o2 = 0.f, o3 = 0.f;
#pragma unroll 4
    for (int s = 0; s < NCH; ++s) {
#pragma unroll
        for (int e = 0; e < 2; ++e) {
            const int r = s * RPS + 2 * g + e;
            const uint2 pk = *reinterpret_cast<const uint2*>(s1sm + r * D + col);
            __nv_bfloat162 p01, p23;
            *reinterpret_cast<uint32_t*>(&p01) = pk.x;
            *reinterpret_cast<uint32_t*>(&p23) = pk.y;

            const float kf = ksm[r];
            const float qf = qsm[r];

            o0 += qf * bf16r(__low2float(p01)  + kf * delta[0]);
            o1 += qf * bf16r(__high2float(p01) + kf * delta[1]);
            o2 += qf * bf16r(__low2float(p23)  + kf * delta[2]);
            o3 += qf * bf16r(__high2float(p23) + kf * delta[3]);
        }
    }

    *reinterpret_cast<float4*>(&red[g][col]) = make_float4(o0, o1, o2, o3);
    __syncthreads();

    // group 0 reduces and writes f32 output (bf16-rounded, matching reference)
    if (g == 0) {
        float sres[4];
#pragma unroll
        for (int j = 0; j < 4; ++j) {
            const float r = red[0][col + j] + red[1][col + j] +
                            red[2][col + j] + red[3][col + j];
            sres[j] = bf16r(r);
        }
        *reinterpret_cast<float4*>(out + (size_t)bh * D + col) =
            make_float4(sres[0], sres[1], sres[2], sres[3]);
    }
}

// ---------------- Generic fallback: runtime DK, DV ----------------
__global__ void __launch_bounds__(128)
deltanet_f32_gen(const float* __restrict__ q,
                 const float* __restrict__ k,
                 const float* __restrict__ v,
                 const float* __restrict__ beta,
                 const float* __restrict__ gate,
                 const float* __restrict__ state,
                 float* __restrict__ out,
                 int DK, int DV)
{
    extern __shared__ float dyn[];   // ks[DK], qs[DK]
    float* ks = dyn;
    float* qs = dyn + DK;

    const int bh = blockIdx.x;
    const int t  = threadIdx.x;

    for (int i = t; i < DK; i += 128) {
        ks[i] = __ldg(k + (size_t)bh * DK + i);
        qs[i] = __ldg(q + (size_t)bh * DK + i);
    }
    __syncthreads();

    const float decay = expf(__ldg(gate + bh));
    const float betaf = __ldg(beta + bh);
    const float* S = state + (size_t)bh * DK * DV;

    for (int j = t; j < DV; j += 128) {
        float acc = 0.0f;
        for (int dk = 0; dk < DK; ++dk)
            acc += ks[dk] * bf16r(__ldg(S + (size_t)dk * DV + j) * decay);

        const float delta = betaf * (__ldg(v + (size_t)bh * DV + j) - acc);

        float o = 0.0f;
        for (int dk = 0; dk < DK; ++dk) {
            const float s1 = bf16r(__ldg(S + (size_t)dk * DV + j) * decay);
            o += qs[dk] * bf16r(s1 + ks[dk] * delta);
        }
        out[(size_t)bh * DV + j] = bf16r(o);
    }
}

extern "C" void kernel_launch(void* const* d_in, const int* in_sizes, int n_in,
                              void* d_out, int out_size)
{
    // Insertion order (q, k, v, beta, gate, state); element counts; all f32.
    const float* q     = (const float*)d_in[0];
    const float* k     = (const float*)d_in[1];
    const float* v     = (const float*)d_in[2];
    const float* beta  = (const float*)d_in[3];
    const float* gate  = (const float*)d_in[4];
    const float* state = (const float*)d_in[5];
    float* out = (float*)d_out;

    const long long BH = in_sizes[3];                 // |beta| = B*H
    const long long DK = (long long)in_sizes[0] / BH; // |q| / BH
    const long long DV = (long long)in_sizes[2] / BH; // |v| / BH

    if (DK == 128 && DV == 128) {
        deltanet_pipe_128<<<(unsigned)BH, 128>>>(q, k, v, beta, gate, state, out);
    } else {
        const size_t shmem = (size_t)(2 * DK) * sizeof(float);
        deltanet_f32_gen<<<(unsigned)BH, 128, shmem>>>(
            q, k, v, beta, gate, state, out, (int)DK, (int)DV);
    }
}

// round 13
// speedup vs baseline: 1.1879x; 1.1879x over previous
#include <cuda_runtime.h>
#include <cuda_bf16.h>
#include <cstdint>

// DeltaNet fused recurrent decode step (all buffers float32; bf16 rounding
// emulated to match the reference exactly).
//   s1  = bf16(exp(gate) * state) ; acc = k^T s1 ; delta = beta*(v - acc)
//   s2  = bf16(s1 + k (outer) delta) ; out = bf16(q^T s2)
//
// One CTA (256 threads) per (b,h): 8 warps x 16 dk-rows, 4 dv-cols/thread.
// State streamed once (float4 __ldcs); decayed bf16 state cached in 32KB smem
// for pass 2. 6 CTAs/SM (37.5KB smem) -> 48 warps. Insertion order, element
// counts, f32 buffers.

static __device__ __forceinline__ float bf16r(float x) {
    return __bfloat162float(__float2bfloat16(x));
}

static constexpr int D = 128;

__global__ void __launch_bounds__(256)
deltanet_f32_256(const float* __restrict__ q,
                 const float* __restrict__ k,
                 const float* __restrict__ v,
                 const float* __restrict__ beta,
                 const float* __restrict__ gate,
                 const float* __restrict__ state,
                 float* __restrict__ out)
{
    __shared__ __align__(16) __nv_bfloat16 s1sm[D * D];  // 32 KB decayed state
    __shared__ float ksm[D];
    __shared__ float qsm[D];
    __shared__ __align__(16) float red[8][D];            // 4 KB cross-warp partials

    const int bh  = blockIdx.x;
    const int t   = threadIdx.x;
    const int g   = t >> 5;       // warp: which 16-row dk slice
    const int c   = t & 31;
    const int col = 4 * c;        // 4 dv columns per thread

    const float* st = state + (size_t)bh * (D * D);

    if (t < D) {
        ksm[t] = __ldg(k + (size_t)bh * D + t);
        qsm[t] = __ldg(q + (size_t)bh * D + t);
    }
    const float decay = expf(__ldg(gate + bh));
    const float betaf = __ldg(beta + bh);
    __syncthreads();

    // ---- Pass 1: s1 = bf16(decay*S) -> smem; acc = k^T s1 ----
    float acc0 = 0.f, acc1 = 0.f, acc2 = 0.f, acc3 = 0.f;

#pragma unroll 8
    for (int i = 0; i < 16; ++i) {
        const int dk = g * 16 + i;
        // float4 streaming load: 402MB state touched exactly once
        const float4 f = __ldcs(reinterpret_cast<const float4*>(st + (size_t)dk * D + col));

        // bf16 round-to-nearest-even after decay (reference stores s1 as bf16)
        const __nv_bfloat162 p01 =
            __float22bfloat162_rn(make_float2(f.x * decay, f.y * decay));
        const __nv_bfloat162 p23 =
            __float22bfloat162_rn(make_float2(f.z * decay, f.w * decay));

        uint2 pk;
        pk.x = *reinterpret_cast<const uint32_t*>(&p01);
        pk.y = *reinterpret_cast<const uint32_t*>(&p23);
        *reinterpret_cast<uint2*>(s1sm + dk * D + col) = pk;

        const float kf = ksm[dk];
        acc0 += kf * __low2float(p01);
        acc1 += kf * __high2float(p01);
        acc2 += kf * __low2float(p23);
        acc3 += kf * __high2float(p23);
    }

    *reinterpret_cast<float4*>(&red[g][col]) = make_float4(acc0, acc1, acc2, acc3);
    __syncthreads();

    float delta[4];
#pragma unroll
    for (int j = 0; j < 4; ++j) {
        float a = 0.f;
#pragma unroll
        for (int w = 0; w < 8; ++w) a += red[w][col + j];
        const float vf = __ldg(v + (size_t)bh * D + col + j);
        delta[j] = betaf * (vf - a);
    }
    __syncthreads();   // red consumed before pass-2 overwrites it

    // ---- Pass 2: out = q^T bf16(s1 + k*delta), s1 from smem (same rows) ----
    float o0 = 0.f, o1 = 0.f, o2 = 0.f, o3 = 0.f;

#pragma unroll 8
    for (int i = 0; i < 16; ++i) {
        const int dk = g * 16 + i;
        const uint2 pk = *reinterpret_cast<const uint2*>(s1sm + dk * D + col);
        __nv_bfloat162 p01, p23;
        *reinterpret_cast<uint32_t*>(&p01) = pk.x;
        *reinterpret_cast<uint32_t*>(&p23) = pk.y;

        const float kf = ksm[dk];
        const float qf = qsm[dk];

        o0 += qf * bf16r(__low2float(p01)  + kf * delta[0]);
        o1 += qf * bf16r(__high2float(p01) + kf * delta[1]);
        o2 += qf * bf16r(__low2float(p23)  + kf * delta[2]);
        o3 += qf * bf16r(__high2float(p23) + kf * delta[3]);
    }

    *reinterpret_cast<float4*>(&red[g][col]) = make_float4(o0, o1, o2, o3);
    __syncthreads();

    // warp 0 reduces and writes f32 output (bf16-rounded, matching reference)
    if (g == 0) {
        float s[4];
#pragma unroll
        for (int j = 0; j < 4; ++j) {
            float r = 0.f;
#pragma unroll
            for (int w = 0; w < 8; ++w) r += red[w][col + j];
            s[j] = bf16r(r);
        }
        *reinterpret_cast<float4*>(out + (size_t)bh * D + col) =
            make_float4(s[0], s[1], s[2], s[3]);
    }
}

// ---------------- Generic fallback: runtime DK, DV ----------------
__global__ void __launch_bounds__(128)
deltanet_f32_gen(const float* __restrict__ q,
                 const float* __restrict__ k,
                 const float* __restrict__ v,
                 const float* __restrict__ beta,
                 const float* __restrict__ gate,
                 const float* __restrict__ state,
                 float* __restrict__ out,
                 int DK, int DV)
{
    extern __shared__ float dyn[];   // ks[DK], qs[DK]
    float* ks = dyn;
    float* qs = dyn + DK;

    const int bh = blockIdx.x;
    const int t  = threadIdx.x;

    for (int i = t; i < DK; i += 128) {
        ks[i] = __ldg(k + (size_t)bh * DK + i);
        qs[i] = __ldg(q + (size_t)bh * DK + i);
    }
    __syncthreads();

    const float decay = expf(__ldg(gate + bh));
    const float betaf = __ldg(beta + bh);
    const float* S = state + (size_t)bh * DK * DV;

    for (int j = t; j < DV; j += 128) {
        float acc = 0.0f;
        for (int dk = 0; dk < DK; ++dk)
            acc += ks[dk] * bf16r(__ldg(S + (size_t)dk * DV + j) * decay);

        const float delta = betaf * (__ldg(v + (size_t)bh * DV + j) - acc);

        float o = 0.0f;
        for (int dk = 0; dk < DK; ++dk) {
            const float s1 = bf16r(__ldg(S + (size_t)dk * DV + j) * decay);
            o += qs[dk] * bf16r(s1 + ks[dk] * delta);
        }
        out[(size_t)bh * DV + j] = bf16r(o);
    }
}

extern "C" void kernel_launch(void* const* d_in, const int* in_sizes, int n_in,
                              void* d_out, int out_size)
{
    // Insertion order (q, k, v, beta, gate, state); element counts; all f32.
    const float* q     = (const float*)d_in[0];
    const float* k     = (const float*)d_in[1];
    const float* v     = (const float*)d_in[2];
    const float* beta  = (const float*)d_in[3];
    const float* gate  = (const float*)d_in[4];
    const float* state = (const float*)d_in[5];
    float* out = (float*)d_out;

    const long long BH = in_sizes[3];                 // |beta| = B*H
    const long long DK = (long long)in_sizes[0] / BH; // |q| / BH
    const long long DV = (long long)in_sizes[2] / BH; // |v| / BH

    if (DK == 128 && DV == 128) {
        deltanet_f32_256<<<(unsigned)BH, 256>>>(q, k, v, beta, gate, state, out);
    } else {
        const size_t shmem = (size_t)(2 * DK) * sizeof(float);
        deltanet_f32_gen<<<(unsigned)BH, 128, shmem>>>(
            q, k, v, beta, gate, state, out, (int)DK, (int)DV);
    }
}